// round 6
// baseline (speedup 1.0000x reference)
#include <cuda_runtime.h>

#define N_NODES 100000
#define DIN     128
#define HDIM    64

// Scratch (device globals; zeroed at module load; k_out re-zeroes g_deg each run)
__device__ float g_deg[N_NODES];   // edge-only degree (self-loop +1 added at use)
__device__ float g_dis[N_NODES];
__device__ float g_p[N_NODES];     // K_A: s = x.w ; after K_B: dis*val
__device__ float g_acc[N_NODES];   // accumulator, init = p (self-loop folded)
__device__ float g_c1;
__device__ float g_c2;

__device__ __forceinline__ int4 ldcs4i(const int* p)   { return __ldcs((const int4*)p); }
__device__ __forceinline__ float4 ldcs4f(const float* p){ return __ldcs((const float4*)p); }

// ---------------------------------------------------------------------------
// K_A (fused): blocks [0, eblocks)  : deg[dst] += ew   (4 edges/thread)
//              blocks [eblocks, ..) : s[i] = x[i].w    (grid-stride, 4 nodes/warp)
// Node blocks redundantly collapse weights (W2@fc_w -> u, W1@u -> w) in smem.
// Block 0 additionally computes the bias constants c1, c2.
// ---------------------------------------------------------------------------
__global__ void k_fusedA(const int* __restrict__ dst, const float* __restrict__ ew,
                         int E,
                         const float* __restrict__ x, int n,
                         const float* __restrict__ W1, const float* __restrict__ b1,
                         const float* __restrict__ W2, const float* __restrict__ b2,
                         const float* __restrict__ fc_w, const float* __restrict__ fc_b,
                         int eblocks, int nwarps_total) {
    if (blockIdx.x < (unsigned)eblocks) {
        // ---- edge work: degree accumulation ----
        int e4 = (blockIdx.x * blockDim.x + threadIdx.x) * 4;
        if (e4 + 3 < E) {
            int4   d = ldcs4i(dst + e4);
            float4 w = ldcs4f(ew + e4);
            atomicAdd(&g_deg[d.x], w.x);
            atomicAdd(&g_deg[d.y], w.y);
            atomicAdd(&g_deg[d.z], w.z);
            atomicAdd(&g_deg[d.w], w.w);
        } else {
            for (int e = e4; e < E; ++e)
                atomicAdd(&g_deg[dst[e]], ew[e]);
        }
        if (blockIdx.x == 0 && threadIdx.x == 0) {
            // c1 = b1 . (W2 @ fc_w),  c2 = b2 . fc_w + fc_b   (tiny, one thread)
            float c1 = 0.f, c2 = 0.f;
            for (int t = 0; t < HDIM; ++t) {
                float u = 0.f;
                for (int j = 0; j < HDIM; ++j) u += W2[t * HDIM + j] * fc_w[j];
                c1 += b1[t] * u;
                c2 += b2[t] * fc_w[t];
            }
            g_c1 = c1;
            g_c2 = c2 + fc_b[0];
        }
        return;
    }

    // ---- node work: collapse weights, then s = x.w ----
    __shared__ float su[HDIM];
    __shared__ __align__(16) float sw[DIN];
    int t = threadIdx.x;
    if (t < HDIM) {
        float acc = 0.f;
        #pragma unroll 8
        for (int j = 0; j < HDIM; ++j) acc += W2[t * HDIM + j] * fc_w[j];
        su[t] = acc;
    }
    __syncthreads();
    if (t < DIN) {
        float acc = 0.f;
        #pragma unroll 8
        for (int j = 0; j < HDIM; ++j) acc += W1[t * HDIM + j] * su[j];
        sw[t] = acc;
    }
    __syncthreads();

    int lane = t & 31;
    float4 wv = ((const float4*)sw)[lane];

    int warp_g = (blockIdx.x - eblocks) * (blockDim.x >> 5) + (t >> 5);
    int stride = nwarps_total * 4;

    for (int base = warp_g * 4; base < n; base += stride) {
        float acc[4];
        if (base + 3 < n) {
            const float4* xr = (const float4*)(x + (size_t)base * DIN);
            float4 v0 = xr[lane];
            float4 v1 = xr[32 + lane];
            float4 v2 = xr[64 + lane];
            float4 v3 = xr[96 + lane];
            acc[0] = v0.x * wv.x + v0.y * wv.y + v0.z * wv.z + v0.w * wv.w;
            acc[1] = v1.x * wv.x + v1.y * wv.y + v1.z * wv.z + v1.w * wv.w;
            acc[2] = v2.x * wv.x + v2.y * wv.y + v2.z * wv.z + v2.w * wv.w;
            acc[3] = v3.x * wv.x + v3.y * wv.y + v3.z * wv.z + v3.w * wv.w;
        } else {
            #pragma unroll
            for (int k = 0; k < 4; ++k) {
                if (base + k < n) {
                    const float4* xr = (const float4*)(x + (size_t)(base + k) * DIN);
                    float4 v = xr[lane];
                    acc[k] = v.x * wv.x + v.y * wv.y + v.z * wv.z + v.w * wv.w;
                } else acc[k] = 0.f;
            }
        }
        #pragma unroll
        for (int o = 16; o; o >>= 1) {
            acc[0] += __shfl_xor_sync(0xFFFFFFFFu, acc[0], o);
            acc[1] += __shfl_xor_sync(0xFFFFFFFFu, acc[1], o);
            acc[2] += __shfl_xor_sync(0xFFFFFFFFu, acc[2], o);
            acc[3] += __shfl_xor_sync(0xFFFFFFFFu, acc[3], o);
        }
        if (lane < 4 && base + lane < n)
            g_p[base + lane] = acc[lane];          // raw s for now
    }
}

// ---------------------------------------------------------------------------
// K_B: dis = rsqrt(1+deg); p = dis*s; acc = p (self-loop term, outer dis later)
// ---------------------------------------------------------------------------
__global__ void k_nodeB(int n) {
    int i = blockIdx.x * blockDim.x + threadIdx.x;
    if (i < n) {
        float dis = rsqrtf(g_deg[i] + 1.0f);
        float p = dis * g_p[i];
        g_dis[i] = dis;
        g_p[i]   = p;
        g_acc[i] = p;
    }
}

// ---------------------------------------------------------------------------
// K prop (both layers): acc[dst] += ew * p[src].  4 edges per thread.
// ---------------------------------------------------------------------------
__global__ void k_prop(const int* __restrict__ ei,
                       const float* __restrict__ ew, int E) {
    int e4 = (blockIdx.x * blockDim.x + threadIdx.x) * 4;
    if (e4 + 3 < E) {
        int4   s = ldcs4i(ei + e4);
        int4   d = ldcs4i(ei + (size_t)E + e4);
        float4 w = ldcs4f(ew + e4);
        float p0 = g_p[s.x], p1 = g_p[s.y], p2 = g_p[s.z], p3 = g_p[s.w];
        atomicAdd(&g_acc[d.x], w.x * p0);
        atomicAdd(&g_acc[d.y], w.y * p1);
        atomicAdd(&g_acc[d.z], w.z * p2);
        atomicAdd(&g_acc[d.w], w.w * p3);
    } else {
        for (int e = e4; e < E; ++e)
            atomicAdd(&g_acc[ei[(size_t)E + e]], ew[e] * g_p[ei[e]]);
    }
}

// ---------------------------------------------------------------------------
// K mid: t = c1 + dis*acc;  p2 = dis*t;  acc = p2 (self-loop of layer 2)
// ---------------------------------------------------------------------------
__global__ void k_mid(int n) {
    int i = blockIdx.x * blockDim.x + threadIdx.x;
    if (i < n) {
        float dis = g_dis[i];
        float t   = fmaf(dis, g_acc[i], g_c1);
        float p2  = dis * t;
        g_p[i]   = p2;
        g_acc[i] = p2;
    }
}

// K out: out = rint(clip(c2 + dis*acc, 0, 10)); re-zero g_deg for graph replay.
__global__ void k_out(float* __restrict__ out, int n) {
    int i = blockIdx.x * blockDim.x + threadIdx.x;
    if (i < n) {
        float v = fmaf(g_dis[i], g_acc[i], g_c2);
        out[i] = rintf(fminf(fmaxf(v, 0.f), 10.f));
        g_deg[i] = 0.0f;
    }
}

extern "C" void kernel_launch(void* const* d_in, const int* in_sizes, int n_in,
                              void* d_out, int out_size) {
    const float* x    = (const float*)d_in[0];
    const int*   ei   = (const int*)d_in[1];    // int32 [2, E]
    const float* ew   = (const float*)d_in[2];
    const float* W1   = (const float*)d_in[3];
    const float* b1   = (const float*)d_in[4];
    const float* W2   = (const float*)d_in[5];
    const float* b2   = (const float*)d_in[6];
    const float* fc_w = (const float*)d_in[7];
    const float* fc_b = (const float*)d_in[8];
    float*       out  = (float*)d_out;

    const int E = in_sizes[2];             // 1600000
    const int N = in_sizes[0] / DIN;       // 100000

    const int TB = 256;
    const int nb_nodes  = (N + TB - 1) / TB;
    const int nb_edges4 = ((E + 3) / 4 + TB - 1) / TB;   // 1563
    const int NODE_BLOCKS = 256;                          // grid-stride s-compute
    const int nwarps_total = NODE_BLOCKS * (TB / 32);

    k_fusedA<<<nb_edges4 + NODE_BLOCKS, TB>>>(ei + E, ew, E, x, N,
                                              W1, b1, W2, b2, fc_w, fc_b,
                                              nb_edges4, nwarps_total);
    k_nodeB<<<nb_nodes, TB>>>(N);
    k_prop<<<nb_edges4, TB>>>(ei, ew, E);
    k_mid<<<nb_nodes, TB>>>(N);
    k_prop<<<nb_edges4, TB>>>(ei, ew, E);
    k_out<<<nb_nodes, TB>>>(out, N);
}

// round 7
// speedup vs baseline: 1.2466x; 1.2466x over previous
#include <cuda_runtime.h>

#define N_NODES 100000
#define DIN     128
#define HDIM    64

// Scratch (device globals; zeroed at module load; k_out re-zeroes g_deg each run)
__device__ float g_deg[N_NODES];   // edge-only degree (self-loop +1 added at use)
__device__ float g_dis[N_NODES];
__device__ float g_p[N_NODES];     // raw s after k_fused; dis*val after nodeB/mid
__device__ float g_acc[N_NODES];   // accumulator, init = p (self-loop folded)
__device__ __align__(16) float g_w[DIN];
__device__ float g_c1;
__device__ float g_c2;

__device__ __forceinline__ int4   ldcs4i(const int* p)   { return __ldcs((const int4*)p); }
__device__ __forceinline__ float4 ldcs4f(const float* p) { return __ldcs((const float4*)p); }

// ---------------------------------------------------------------------------
// K0: weight collapse (1 block, 128 threads).
//   u = W2 @ fc_w (64), w = W1 @ u (128), c1 = b1.u, c2 = b2.fc_w + fc_b
// ---------------------------------------------------------------------------
__global__ void k_init(const float* __restrict__ W1, const float* __restrict__ b1,
                       const float* __restrict__ W2, const float* __restrict__ b2,
                       const float* __restrict__ fc_w, const float* __restrict__ fc_b) {
    __shared__ float u[HDIM];
    int t = threadIdx.x;
    if (t < HDIM) {
        float acc = 0.f;
        #pragma unroll 8
        for (int j = 0; j < HDIM; ++j) acc += W2[t * HDIM + j] * fc_w[j];
        u[t] = acc;
    }
    __syncthreads();
    if (t < DIN) {
        float acc = 0.f;
        #pragma unroll 8
        for (int j = 0; j < HDIM; ++j) acc += W1[t * HDIM + j] * u[j];
        g_w[t] = acc;
    }
    if (t == 0) {
        float c1 = 0.f, c2 = 0.f;
        for (int j = 0; j < HDIM; ++j) { c1 += b1[j] * u[j]; c2 += b2[j] * fc_w[j]; }
        g_c1 = c1;
        g_c2 = c2 + fc_b[0];
    }
}

// ---------------------------------------------------------------------------
// K1 (fused, node blocks FIRST):
//   blocks [0, nodeBlocks):          s[i] = x[i].w   (one 4-node tile per warp)
//   blocks [nodeBlocks, +edgeBlocks): deg[dst] += ew (4 edges per thread)
// ---------------------------------------------------------------------------
__global__ void k_fused(const float* __restrict__ x, int n, int nodeBlocks,
                        const int* __restrict__ dst, const float* __restrict__ ew, int E) {
    if ((int)blockIdx.x < nodeBlocks) {
        // ---- node work: s = x.w ----
        __shared__ __align__(16) float sw[DIN];
        int t = threadIdx.x;
        if (t < DIN) sw[t] = g_w[t];
        __syncthreads();

        int warp = blockIdx.x * (blockDim.x >> 5) + (t >> 5);
        int lane = t & 31;
        int base = warp * 4;
        if (base >= n) return;

        float4 wv = ((const float4*)sw)[lane];
        float acc[4];
        if (base + 3 < n) {
            const float4* xr = (const float4*)(x + (size_t)base * DIN);
            float4 v0 = xr[lane];
            float4 v1 = xr[32 + lane];
            float4 v2 = xr[64 + lane];
            float4 v3 = xr[96 + lane];
            acc[0] = v0.x * wv.x + v0.y * wv.y + v0.z * wv.z + v0.w * wv.w;
            acc[1] = v1.x * wv.x + v1.y * wv.y + v1.z * wv.z + v1.w * wv.w;
            acc[2] = v2.x * wv.x + v2.y * wv.y + v2.z * wv.z + v2.w * wv.w;
            acc[3] = v3.x * wv.x + v3.y * wv.y + v3.z * wv.z + v3.w * wv.w;
        } else {
            #pragma unroll
            for (int k = 0; k < 4; ++k) {
                if (base + k < n) {
                    const float4* xr = (const float4*)(x + (size_t)(base + k) * DIN);
                    float4 v = xr[lane];
                    acc[k] = v.x * wv.x + v.y * wv.y + v.z * wv.z + v.w * wv.w;
                } else acc[k] = 0.f;
            }
        }
        #pragma unroll
        for (int o = 16; o; o >>= 1) {
            acc[0] += __shfl_xor_sync(0xFFFFFFFFu, acc[0], o);
            acc[1] += __shfl_xor_sync(0xFFFFFFFFu, acc[1], o);
            acc[2] += __shfl_xor_sync(0xFFFFFFFFu, acc[2], o);
            acc[3] += __shfl_xor_sync(0xFFFFFFFFu, acc[3], o);
        }
        if (lane < 4 && base + lane < n)
            g_p[base + lane] = acc[lane];          // raw s; dis applied in nodeB
    } else {
        // ---- edge work: degree accumulation ----
        int e4 = ((blockIdx.x - nodeBlocks) * blockDim.x + threadIdx.x) * 4;
        if (e4 + 3 < E) {
            int4   d = ldcs4i(dst + e4);
            float4 w = ldcs4f(ew + e4);
            atomicAdd(&g_deg[d.x], w.x);
            atomicAdd(&g_deg[d.y], w.y);
            atomicAdd(&g_deg[d.z], w.z);
            atomicAdd(&g_deg[d.w], w.w);
        } else {
            for (int e = e4; e < E; ++e)
                atomicAdd(&g_deg[dst[e]], ew[e]);
        }
    }
}

// ---------------------------------------------------------------------------
// K2: dis = rsqrt(1+deg); p = dis*s; acc = p.  float4-vectorized.
// ---------------------------------------------------------------------------
__global__ void k_nodeB(int n) {
    int i = blockIdx.x * blockDim.x + threadIdx.x;
    int nvec = n >> 2;
    if (i < nvec) {
        float4 dg = ((const float4*)g_deg)[i];
        float4 s  = ((const float4*)g_p)[i];
        float4 ds;
        ds.x = rsqrtf(dg.x + 1.f); ds.y = rsqrtf(dg.y + 1.f);
        ds.z = rsqrtf(dg.z + 1.f); ds.w = rsqrtf(dg.w + 1.f);
        float4 p;
        p.x = ds.x * s.x; p.y = ds.y * s.y; p.z = ds.z * s.z; p.w = ds.w * s.w;
        ((float4*)g_dis)[i] = ds;
        ((float4*)g_p)[i]   = p;
        ((float4*)g_acc)[i] = p;
    } else if (i == nvec) {
        for (int j = nvec * 4; j < n; ++j) {
            float dis = rsqrtf(g_deg[j] + 1.f);
            float p = dis * g_p[j];
            g_dis[j] = dis; g_p[j] = p; g_acc[j] = p;
        }
    }
}

// ---------------------------------------------------------------------------
// K prop (both layers): acc[dst] += ew * p[src].  4 edges per thread.
// ---------------------------------------------------------------------------
__global__ void k_prop(const int* __restrict__ ei,
                       const float* __restrict__ ew, int E) {
    int e4 = (blockIdx.x * blockDim.x + threadIdx.x) * 4;
    if (e4 + 3 < E) {
        int4   s = ldcs4i(ei + e4);
        int4   d = ldcs4i(ei + (size_t)E + e4);
        float4 w = ldcs4f(ew + e4);
        float p0 = g_p[s.x], p1 = g_p[s.y], p2 = g_p[s.z], p3 = g_p[s.w];
        atomicAdd(&g_acc[d.x], w.x * p0);
        atomicAdd(&g_acc[d.y], w.y * p1);
        atomicAdd(&g_acc[d.z], w.z * p2);
        atomicAdd(&g_acc[d.w], w.w * p3);
    } else {
        for (int e = e4; e < E; ++e)
            atomicAdd(&g_acc[ei[(size_t)E + e]], ew[e] * g_p[ei[e]]);
    }
}

// ---------------------------------------------------------------------------
// K mid: t = c1 + dis*acc;  p2 = dis*t;  acc = p2.  float4-vectorized.
// ---------------------------------------------------------------------------
__global__ void k_mid(int n) {
    int i = blockIdx.x * blockDim.x + threadIdx.x;
    int nvec = n >> 2;
    float c1 = g_c1;
    if (i < nvec) {
        float4 ds = ((const float4*)g_dis)[i];
        float4 a  = ((const float4*)g_acc)[i];
        float4 p;
        p.x = ds.x * fmaf(ds.x, a.x, c1);
        p.y = ds.y * fmaf(ds.y, a.y, c1);
        p.z = ds.z * fmaf(ds.z, a.z, c1);
        p.w = ds.w * fmaf(ds.w, a.w, c1);
        ((float4*)g_p)[i]   = p;
        ((float4*)g_acc)[i] = p;
    } else if (i == nvec) {
        for (int j = nvec * 4; j < n; ++j) {
            float dis = g_dis[j];
            float p = dis * fmaf(dis, g_acc[j], c1);
            g_p[j] = p; g_acc[j] = p;
        }
    }
}

// K out: out = rint(clip(c2 + dis*acc, 0, 10)); re-zero g_deg for graph replay.
__global__ void k_out(float* __restrict__ out, int n) {
    int i = blockIdx.x * blockDim.x + threadIdx.x;
    int nvec = n >> 2;
    float c2 = g_c2;
    if (i < nvec) {
        float4 ds = ((const float4*)g_dis)[i];
        float4 a  = ((const float4*)g_acc)[i];
        float4 o;
        o.x = rintf(fminf(fmaxf(fmaf(ds.x, a.x, c2), 0.f), 10.f));
        o.y = rintf(fminf(fmaxf(fmaf(ds.y, a.y, c2), 0.f), 10.f));
        o.z = rintf(fminf(fmaxf(fmaf(ds.z, a.z, c2), 0.f), 10.f));
        o.w = rintf(fminf(fmaxf(fmaf(ds.w, a.w, c2), 0.f), 10.f));
        ((float4*)out)[i] = o;
        ((float4*)g_deg)[i] = make_float4(0.f, 0.f, 0.f, 0.f);
    } else if (i == nvec) {
        for (int j = nvec * 4; j < n; ++j) {
            out[j] = rintf(fminf(fmaxf(fmaf(g_dis[j], g_acc[j], c2), 0.f), 10.f));
            g_deg[j] = 0.f;
        }
    }
}

extern "C" void kernel_launch(void* const* d_in, const int* in_sizes, int n_in,
                              void* d_out, int out_size) {
    const float* x    = (const float*)d_in[0];
    const int*   ei   = (const int*)d_in[1];    // int32 [2, E]
    const float* ew   = (const float*)d_in[2];
    const float* W1   = (const float*)d_in[3];
    const float* b1   = (const float*)d_in[4];
    const float* W2   = (const float*)d_in[5];
    const float* b2   = (const float*)d_in[6];
    const float* fc_w = (const float*)d_in[7];
    const float* fc_b = (const float*)d_in[8];
    float*       out  = (float*)d_out;

    const int E = in_sizes[2];             // 1600000
    const int N = in_sizes[0] / DIN;       // 100000

    const int TB = 256;
    const int nb_edges4 = ((E + 3) / 4 + TB - 1) / TB;                 // 1563
    const int nodeBlocks = (((N + 3) / 4) + (TB / 32) - 1) / (TB / 32); // 4 nodes/warp
    const int nb_vec = ((N >> 2) + 1 + TB - 1) / TB;                   // float4 kernels

    k_init<<<1, 128>>>(W1, b1, W2, b2, fc_w, fc_b);
    k_fused<<<nodeBlocks + nb_edges4, TB>>>(x, N, nodeBlocks, ei + E, ew, E);
    k_nodeB<<<nb_vec, TB>>>(N);
    k_prop<<<nb_edges4, TB>>>(ei, ew, E);
    k_mid<<<nb_vec, TB>>>(N);
    k_prop<<<nb_edges4, TB>>>(ei, ew, E);
    k_out<<<nb_vec, TB>>>(out, N);
}